// round 1
// baseline (speedup 1.0000x reference)
#include <cuda_runtime.h>
#include <math_constants.h>

#define NN 50000
#define EE 600000
#define DD 128
#define LL 12

// ---- persistent device scratch (no allocs allowed) ----
__device__ float g_bufA[NN * DD];
__device__ float g_bufB[NN * DD];
__device__ float g_agg [NN * DD];
__device__ int   g_rowptr[NN + 1];
__device__ int   g_woff [NN];
__device__ int   g_csrc [EE];
__device__ int   g_deg  [NN];

// ---------------- init / CSR build ----------------

__global__ void k_copy_x(const float* __restrict__ x, float* __restrict__ dst) {
    int i = blockIdx.x * blockDim.x + threadIdx.x;           // float4 index
    const int total = NN * DD / 4;
    if (i < total) {
        ((float4*)dst)[i] = ((const float4*)x)[i];
    }
}

__global__ void k_zero_deg() {
    int i = blockIdx.x * blockDim.x + threadIdx.x;
    if (i < NN) g_deg[i] = 0;
}

__global__ void k_hist(const int* __restrict__ ei) {
    int e = blockIdx.x * blockDim.x + threadIdx.x;
    if (e < EE) atomicAdd(&g_deg[ei[EE + e]], 1);            // dst row
}

// single-block exclusive scan over g_deg -> g_rowptr, g_woff
__global__ void k_scan() {
    __shared__ int part[1024];
    const int tid = threadIdx.x;
    const int CH = (NN + 1023) / 1024;                       // 49
    int base = tid * CH;
    int s = 0;
    for (int i = 0; i < CH; i++) {
        int idx = base + i;
        if (idx < NN) s += g_deg[idx];
    }
    part[tid] = s;
    __syncthreads();
    // Hillis-Steele inclusive scan
    for (int off = 1; off < 1024; off <<= 1) {
        int v = (tid >= off) ? part[tid - off] : 0;
        __syncthreads();
        part[tid] += v;
        __syncthreads();
    }
    int run = part[tid] - s;                                 // exclusive start
    for (int i = 0; i < CH; i++) {
        int idx = base + i;
        if (idx < NN) {
            g_rowptr[idx] = run;
            g_woff[idx]   = run;
            run += g_deg[idx];
        }
    }
    if (tid == 1023) g_rowptr[NN] = part[1023];
}

__global__ void k_fill(const int* __restrict__ ei) {
    int e = blockIdx.x * blockDim.x + threadIdx.x;
    if (e < EE) {
        int d = ei[EE + e];
        int p = atomicAdd(&g_woff[d], 1);
        g_csrc[p] = ei[e];                                   // src row
    }
}

// ---------------- aggregation (CSR gather-reduce) ----------------
// AGGR: 0 sum, 1 mean, 2 max
template <int AGGR>
__global__ void k_agg(const float* __restrict__ h) {
    const int v = blockIdx.x;
    const int t = threadIdx.x;                               // 0..127 (feature dim)
    __shared__ int ssrc[128];
    const int beg = g_rowptr[v];
    const int end = g_rowptr[v + 1];
    float acc = (AGGR == 2) ? -CUDART_INF_F : 0.f;
    for (int base = beg; base < end; base += 128) {
        int cnt = min(128, end - base);
        __syncthreads();
        if (t < cnt) ssrc[t] = g_csrc[base + t];
        __syncthreads();
        #pragma unroll 4
        for (int j = 0; j < cnt; j++) {
            float val = __ldg(&h[ssrc[j] * DD + t]);
            if (AGGR == 2) acc = fmaxf(acc, val);
            else           acc += val;
        }
    }
    if (AGGR == 1) {
        int deg = end - beg;
        if (deg > 0) acc *= (1.0f / (float)deg);
    }
    if (AGGR == 2) {
        if (isinf(acc) && acc < 0.f) acc = 0.f;              // empty segment -> 0
    }
    g_agg[v * DD + t] = acc;
}

// ---------------- fused dual GEMM + bias + ReLU ----------------
// C[n][j] = sum_k A1[n,k]*Wa[j,k]  (+ sum_k A2[n,k]*Wb[j,k] if A2)  + bias[j], opt relu
// Tile: 128 nodes x 128 outputs, 256 threads, 8x8 micro-tile, K staged 8 (k-major smem).
__global__ __launch_bounds__(256, 2)
void k_gemm(const float* __restrict__ A1, const float* __restrict__ A2,
            const float* __restrict__ Wa, const float* __restrict__ Wb,
            const float* __restrict__ bias,
            float* __restrict__ Out, int relu) {
    __shared__ float As[8][128];
    __shared__ float Ws[8][128];
    const int t = threadIdx.x;
    const int n0 = blockIdx.x * 128;
    const int r = t >> 4;                                    // 0..15 -> nodes r*8..r*8+7
    const int c = t & 15;                                    // 0..15 -> outs  c*8..c*8+7

    float acc[8][8];
    #pragma unroll
    for (int i = 0; i < 8; i++)
        #pragma unroll
        for (int j = 0; j < 8; j++) acc[i][j] = 0.f;

    const int Ktot = A2 ? 256 : 128;
    const int ln = t >> 1;                                   // loader row 0..127
    const int lq = (t & 1) * 4;                              // 0 or 4

    for (int kk = 0; kk < Ktot; kk += 8) {
        const float* Ag = (kk < 128) ? A1 : A2;
        const float* Wg = (kk < 128) ? Wa : Wb;
        const int ko = (kk < 128) ? kk : (kk - 128);

        int gn = n0 + ln; if (gn >= NN) gn = NN - 1;         // clamp (stores guarded)
        float4 av = *(const float4*)(Ag + (size_t)gn * DD + ko + lq);
        float4 wv = *(const float4*)(Wg + (size_t)ln * DD + ko + lq);

        __syncthreads();                                     // prior-iter reads done
        As[lq + 0][ln] = av.x; As[lq + 1][ln] = av.y;
        As[lq + 2][ln] = av.z; As[lq + 3][ln] = av.w;
        Ws[lq + 0][ln] = wv.x; Ws[lq + 1][ln] = wv.y;
        Ws[lq + 2][ln] = wv.z; Ws[lq + 3][ln] = wv.w;
        __syncthreads();

        #pragma unroll
        for (int k = 0; k < 8; k++) {
            float4 a0 = *(const float4*)&As[k][r * 8];
            float4 a1 = *(const float4*)&As[k][r * 8 + 4];
            float4 w0 = *(const float4*)&Ws[k][c * 8];
            float4 w1 = *(const float4*)&Ws[k][c * 8 + 4];
            float a[8] = {a0.x, a0.y, a0.z, a0.w, a1.x, a1.y, a1.z, a1.w};
            float w[8] = {w0.x, w0.y, w0.z, w0.w, w1.x, w1.y, w1.z, w1.w};
            #pragma unroll
            for (int i = 0; i < 8; i++)
                #pragma unroll
                for (int j = 0; j < 8; j++)
                    acc[i][j] = fmaf(a[i], w[j], acc[i][j]);
        }
    }

    // epilogue
    #pragma unroll
    for (int i = 0; i < 8; i++) {
        int n = n0 + r * 8 + i;
        if (n >= NN) break;
        #pragma unroll
        for (int j = 0; j < 8; j++) {
            int jj = c * 8 + j;
            float v = acc[i][j] + bias[jj];
            if (relu) v = fmaxf(v, 0.f);
            Out[(size_t)n * DD + jj] = v;
        }
    }
}

// ---------------- final 128 -> 2 head ----------------
__global__ void k_head(const float* __restrict__ h, const float* __restrict__ W2,
                       const float* __restrict__ b2, float* __restrict__ out) {
    const int n = blockIdx.x;
    const int t = threadIdx.x;                               // 128
    float v  = h[(size_t)n * DD + t];
    float p0 = v * __ldg(&W2[t]);
    float p1 = v * __ldg(&W2[DD + t]);
    #pragma unroll
    for (int off = 16; off > 0; off >>= 1) {
        p0 += __shfl_down_sync(0xffffffff, p0, off);
        p1 += __shfl_down_sync(0xffffffff, p1, off);
    }
    __shared__ float s0[4], s1[4];
    int w = t >> 5, lane = t & 31;
    if (lane == 0) { s0[w] = p0; s1[w] = p1; }
    __syncthreads();
    if (t == 0) {
        out[n * 2 + 0] = s0[0] + s0[1] + s0[2] + s0[3] + b2[0];
        out[n * 2 + 1] = s1[0] + s1[1] + s1[2] + s1[3] + b2[1];
    }
}

// ---------------- launch ----------------
extern "C" void kernel_launch(void* const* d_in, const int* in_sizes, int n_in,
                              void* d_out, int out_size) {
    const float* x  = (const float*)d_in[0];
    const int*   ei = (const int*)  d_in[1];
    const float* Wl = (const float*)d_in[2];
    const float* bl = (const float*)d_in[3];
    const float* Wr = (const float*)d_in[4];
    const float* W1 = (const float*)d_in[5];
    const float* b1 = (const float*)d_in[6];
    const float* W2 = (const float*)d_in[7];
    const float* b2 = (const float*)d_in[8];
    float* out = (float*)d_out;

    float *bufA, *bufB, *agg;
    cudaGetSymbolAddress((void**)&bufA, g_bufA);
    cudaGetSymbolAddress((void**)&bufB, g_bufB);
    cudaGetSymbolAddress((void**)&agg,  g_agg);

    k_copy_x<<<(NN * DD / 4 + 255) / 256, 256>>>(x, bufA);
    k_zero_deg<<<(NN + 255) / 256, 256>>>();
    k_hist<<<(EE + 255) / 256, 256>>>(ei);
    k_scan<<<1, 1024>>>();
    k_fill<<<(EE + 255) / 256, 256>>>(ei);

    static const int aggrs[LL] = {0, 1, 2, 0, 1, 2, 0, 1, 2, 0, 2, 1};
    const int gemm_grid = (NN + 127) / 128;

    float* hcur = bufA;
    float* hnxt = bufB;
    for (int i = 0; i < LL; i++) {
        switch (aggrs[i]) {
            case 0: k_agg<0><<<NN, 128>>>(hcur); break;
            case 1: k_agg<1><<<NN, 128>>>(hcur); break;
            default: k_agg<2><<<NN, 128>>>(hcur); break;
        }
        k_gemm<<<gemm_grid, 256>>>(agg, hcur,
                                   Wl + (size_t)i * DD * DD,
                                   Wr + (size_t)i * DD * DD,
                                   bl + (size_t)i * DD,
                                   hnxt, 1);
        float* tmp = hcur; hcur = hnxt; hnxt = tmp;
    }

    // relu(h @ W1^T + b1) -> agg
    k_gemm<<<gemm_grid, 256>>>(hcur, nullptr, W1, nullptr, b1, agg, 1);
    // agg @ W2^T + b2 -> out
    k_head<<<NN, 128>>>(agg, W2, b2, out);
}

// round 3
// speedup vs baseline: 2.2110x; 2.2110x over previous
#include <cuda_runtime.h>
#include <cuda_bf16.h>
#include <math_constants.h>
#include <cstdint>

#define NN 50000
#define EE 600000
#define DD 128
#define LL 12
#define GRID_G ((NN + 127) / 128)   // 391

// ---------------- persistent device scratch ----------------
__device__ float g_h0[NN * DD];
__device__ float g_h1[NN * DD];
__device__ __nv_bfloat16 g_Ahi0[NN * 256];
__device__ __nv_bfloat16 g_Alo0[NN * 256];
__device__ __nv_bfloat16 g_Ahi1[NN * 256];
__device__ __nv_bfloat16 g_Alo1[NN * 256];
__device__ __nv_bfloat16 g_Bhi[LL * 128 * 256];
__device__ __nv_bfloat16 g_Blo[LL * 128 * 256];
__device__ __nv_bfloat16 g_W1hi[128 * 128];
__device__ __nv_bfloat16 g_W1lo[128 * 128];
__device__ int g_rowptr[NN + 1];
__device__ int g_woff[NN];
__device__ int g_csrc[EE];
__device__ int g_deg[NN];
__device__ int g_part[256];
__device__ int g_partscan[256];

// ---------------- helpers ----------------
__device__ __forceinline__ uint32_t s2u(const void* p) {
    uint32_t a;
    asm("{ .reg .u64 t; cvta.to.shared.u64 t, %1; cvt.u32.u64 %0, t; }" : "=r"(a) : "l"(p));
    return a;
}
__device__ __forceinline__ void ldsm4(uint32_t& r0, uint32_t& r1, uint32_t& r2, uint32_t& r3,
                                      uint32_t addr) {
    asm volatile("ldmatrix.sync.aligned.m8n8.x4.shared.b16 {%0,%1,%2,%3}, [%4];"
                 : "=r"(r0), "=r"(r1), "=r"(r2), "=r"(r3) : "r"(addr));
}
__device__ __forceinline__ void mmabf(float* c, const uint32_t* a, uint32_t b0, uint32_t b1) {
    asm volatile(
        "mma.sync.aligned.m16n8k16.row.col.f32.bf16.bf16.f32 "
        "{%0,%1,%2,%3}, {%4,%5,%6,%7}, {%8,%9}, {%0,%1,%2,%3};"
        : "+f"(c[0]), "+f"(c[1]), "+f"(c[2]), "+f"(c[3])
        : "r"(a[0]), "r"(a[1]), "r"(a[2]), "r"(a[3]), "r"(b0), "r"(b1));
}
__device__ __forceinline__ uint32_t pack2bf(float a, float b) {
    __nv_bfloat16 ha = __float2bfloat16(a), hb = __float2bfloat16(b);
    return ((uint32_t)__bfloat16_as_ushort(hb) << 16) | (uint32_t)__bfloat16_as_ushort(ha);
}

// ---------------- CSR build ----------------
__global__ void k_zero_deg() {
    int i = blockIdx.x * blockDim.x + threadIdx.x;
    if (i < NN) g_deg[i] = 0;
}
__global__ void k_hist(const int* __restrict__ ei) {
    int e = blockIdx.x * blockDim.x + threadIdx.x;
    if (e < EE) atomicAdd(&g_deg[ei[EE + e]], 1);
}
__global__ void k_blocksum() {
    __shared__ int sm[256];
    int t = threadIdx.x;
    int i = blockIdx.x * 256 + t;
    sm[t] = (i < NN) ? g_deg[i] : 0;
    __syncthreads();
    for (int o = 128; o > 0; o >>= 1) {
        if (t < o) sm[t] += sm[t + o];
        __syncthreads();
    }
    if (t == 0) g_part[blockIdx.x] = sm[0];
}
__global__ void k_scanpart() {
    __shared__ int sm[256];
    int t = threadIdx.x;
    int v = (t < 196) ? g_part[t] : 0;
    sm[t] = v;
    __syncthreads();
    for (int o = 1; o < 256; o <<= 1) {
        int u = (t >= o) ? sm[t - o] : 0;
        __syncthreads();
        sm[t] += u;
        __syncthreads();
    }
    g_partscan[t] = sm[t] - v;
    if (t == 0) g_rowptr[NN] = EE;
}
__global__ void k_rowptr() {
    __shared__ int sm[256];
    int t = threadIdx.x;
    int i = blockIdx.x * 256 + t;
    int v = (i < NN) ? g_deg[i] : 0;
    sm[t] = v;
    __syncthreads();
    for (int o = 1; o < 256; o <<= 1) {
        int u = (t >= o) ? sm[t - o] : 0;
        __syncthreads();
        sm[t] += u;
        __syncthreads();
    }
    if (i < NN) {
        int ex = g_partscan[blockIdx.x] + sm[t] - v;
        g_rowptr[i] = ex;
        g_woff[i] = ex;
    }
}
__global__ void k_fill(const int* __restrict__ ei) {
    int e = blockIdx.x * blockDim.x + threadIdx.x;
    if (e < EE) {
        int d = ei[EE + e];
        int p = atomicAdd(&g_woff[d], 1);
        g_csrc[p] = ei[e];
    }
}

// ---------------- bf16 split preprocessing ----------------
__global__ void k_split_x(const float* __restrict__ x) {
    int i = blockIdx.x * 256 + threadIdx.x;
    if (i < NN * DD) {
        int n = i >> 7, k = i & 127;
        float v = x[i];
        __nv_bfloat16 h = __float2bfloat16(v);
        g_Ahi0[n * 256 + 128 + k] = h;
        g_Alo0[n * 256 + 128 + k] = __float2bfloat16(v - __bfloat162float(h));
    }
}
__global__ void k_wprep(const float* __restrict__ Wl, const float* __restrict__ Wr,
                        const float* __restrict__ W1) {
    int i = blockIdx.x * 256 + threadIdx.x;
    const int tot = LL * 128 * 256;
    if (i < tot) {
        int l = i / 32768;
        int r = (i >> 8) & 127;
        int c = i & 255;
        float v = (c < 128) ? Wl[l * 16384 + r * 128 + c] : Wr[l * 16384 + r * 128 + (c - 128)];
        __nv_bfloat16 h = __float2bfloat16(v);
        g_Bhi[i] = h;
        g_Blo[i] = __float2bfloat16(v - __bfloat162float(h));
    } else {
        int j = i - tot;
        if (j < 16384) {
            float v = W1[j];
            __nv_bfloat16 h = __float2bfloat16(v);
            g_W1hi[j] = h;
            g_W1lo[j] = __float2bfloat16(v - __bfloat162float(h));
        }
    }
}

// ---------------- aggregation: warp per node ----------------
template <int AGGR>
__global__ void k_agg(const float* __restrict__ h,
                      __nv_bfloat16* __restrict__ Ahi, __nv_bfloat16* __restrict__ Alo) {
    int wid = threadIdx.x >> 5, lane = threadIdx.x & 31;
    int v = blockIdx.x * 8 + wid;
    if (v >= NN) return;
    int beg = g_rowptr[v], end = g_rowptr[v + 1];
    float a0, a1, a2, a3;
    if (AGGR == 2) { a0 = a1 = a2 = a3 = -CUDART_INF_F; }
    else           { a0 = a1 = a2 = a3 = 0.f; }
    int j = beg;
    for (; j + 1 < end; j += 2) {
        int s0 = __ldg(&g_csrc[j]);
        int s1 = __ldg(&g_csrc[j + 1]);
        float4 x0 = *(const float4*)(h + (size_t)s0 * DD + lane * 4);
        float4 x1 = *(const float4*)(h + (size_t)s1 * DD + lane * 4);
        if (AGGR == 2) {
            a0 = fmaxf(a0, fmaxf(x0.x, x1.x)); a1 = fmaxf(a1, fmaxf(x0.y, x1.y));
            a2 = fmaxf(a2, fmaxf(x0.z, x1.z)); a3 = fmaxf(a3, fmaxf(x0.w, x1.w));
        } else {
            a0 += x0.x + x1.x; a1 += x0.y + x1.y; a2 += x0.z + x1.z; a3 += x0.w + x1.w;
        }
    }
    if (j < end) {
        int s0 = __ldg(&g_csrc[j]);
        float4 x0 = *(const float4*)(h + (size_t)s0 * DD + lane * 4);
        if (AGGR == 2) {
            a0 = fmaxf(a0, x0.x); a1 = fmaxf(a1, x0.y);
            a2 = fmaxf(a2, x0.z); a3 = fmaxf(a3, x0.w);
        } else {
            a0 += x0.x; a1 += x0.y; a2 += x0.z; a3 += x0.w;
        }
    }
    if (AGGR == 1) {
        int deg = end - beg;
        float inv = (deg > 0) ? (1.0f / (float)deg) : 0.f;
        a0 *= inv; a1 *= inv; a2 *= inv; a3 *= inv;
    }
    if (AGGR == 2) {
        if (isinf(a0) && a0 < 0.f) a0 = 0.f;
        if (isinf(a1) && a1 < 0.f) a1 = 0.f;
        if (isinf(a2) && a2 < 0.f) a2 = 0.f;
        if (isinf(a3) && a3 < 0.f) a3 = 0.f;
    }
    __nv_bfloat16 h0 = __float2bfloat16(a0), h1 = __float2bfloat16(a1);
    __nv_bfloat16 h2 = __float2bfloat16(a2), h3 = __float2bfloat16(a3);
    uint32_t hi01 = ((uint32_t)__bfloat16_as_ushort(h1) << 16) | __bfloat16_as_ushort(h0);
    uint32_t hi23 = ((uint32_t)__bfloat16_as_ushort(h3) << 16) | __bfloat16_as_ushort(h2);
    uint32_t lo01 = pack2bf(a0 - __bfloat162float(h0), a1 - __bfloat162float(h1));
    uint32_t lo23 = pack2bf(a2 - __bfloat162float(h2), a3 - __bfloat162float(h3));
    *(uint2*)(Ahi + (size_t)v * 256 + lane * 4) = make_uint2(hi01, hi23);
    *(uint2*)(Alo + (size_t)v * 256 + lane * 4) = make_uint2(lo01, lo23);
}

// ---------------- HMMA bf16x3 GEMM ----------------
// C = Ahi.Bhi + Ahi.Blo + Alo.Bhi  (A [M,Kd] k-major, B [128,Kd] k-major), +bias, relu.
// Block: 128x128, 8 warps (4 in M x 2 in N), warp tile 32x64. K chunk = 32.
// Smem rows padded to 40 halves (80 B): bank group (5*row + q) % 8 -> conflict-free ldmatrix.
#define SROW 40
__global__ __launch_bounds__(256, 2)
void k_tgemm(const __nv_bfloat16* __restrict__ Ahi, const __nv_bfloat16* __restrict__ Alo,
             int astride,
             const __nv_bfloat16* __restrict__ Bhi, const __nv_bfloat16* __restrict__ Blo,
             int Kd, const float* __restrict__ bias, float* __restrict__ outF,
             __nv_bfloat16* outHi, __nv_bfloat16* outLo) {
    __shared__ __nv_bfloat16 sAhi[128 * SROW];
    __shared__ __nv_bfloat16 sAlo[128 * SROW];
    __shared__ __nv_bfloat16 sBhi[128 * SROW];
    __shared__ __nv_bfloat16 sBlo[128 * SROW];
    __shared__ float sbias[128];

    const int t = threadIdx.x;
    const int lane = t & 31;
    const int wid = t >> 5;
    const int mw = wid & 3;        // M group: rows mw*32 .. +32
    const int nw = wid >> 2;       // N group: cols nw*64 .. +64
    const int n0 = blockIdx.x * 128;

    if (t < 128) sbias[t] = bias[t];

    const uint32_t uAhi = s2u(sAhi), uAlo = s2u(sAlo);
    const uint32_t uBhi = s2u(sBhi), uBlo = s2u(sBlo);
    // ldmatrix base offsets (bytes)
    const uint32_t aoff = (uint32_t)((mw * 32 + (lane & 15)) * 80 + (lane >> 4) * 16);
    const uint32_t boff = (uint32_t)((nw * 64 + ((lane >> 3) & 1) * 8 + (lane & 7)) * 80 +
                                     (lane >> 4) * 16);

    float acc[2][8][4];
    #pragma unroll
    for (int mi = 0; mi < 2; mi++)
        #pragma unroll
        for (int ni = 0; ni < 8; ni++)
            #pragma unroll
            for (int q = 0; q < 4; q++) acc[mi][ni][q] = 0.f;

    const int nch = Kd >> 5;
    for (int c = 0; c < nch; c++) {
        const int kk = c << 5;
        __syncthreads();
        // stage 4 arrays x 128 rows x 32 halves; 2048 uint4 total, 8 per thread
        #pragma unroll
        for (int i = 0; i < 8; i++) {
            int idx = i * 256 + t;
            int arr = idx >> 9;
            int row = (idx >> 2) & 127;
            int q = idx & 3;
            uint4 v;
            if (arr == 0 || arr == 1) {
                const __nv_bfloat16* A = (arr == 0) ? Ahi : Alo;
                int gr = n0 + row; if (gr >= NN) gr = NN - 1;
                v = *(const uint4*)(A + (size_t)gr * astride + kk + q * 8);
            } else {
                const __nv_bfloat16* B = (arr == 2) ? Bhi : Blo;
                v = *(const uint4*)(B + (size_t)row * Kd + kk + q * 8);
            }
            __nv_bfloat16* s = (arr == 0) ? sAhi : (arr == 1) ? sAlo : (arr == 2) ? sBhi : sBlo;
            *(uint4*)(s + row * SROW + q * 8) = v;
        }
        __syncthreads();

        #pragma unroll
        for (int ks = 0; ks < 2; ks++) {
            const uint32_t ko = ks * 32;
            uint32_t ah[2][4], al[2][4], b[4][4];
            ldsm4(ah[0][0], ah[0][1], ah[0][2], ah[0][3], uAhi + aoff + ko);
            ldsm4(ah[1][0], ah[1][1], ah[1][2], ah[1][3], uAhi + aoff + 16 * 80 + ko);
            #pragma unroll
            for (int g = 0; g < 4; g++)
                ldsm4(b[g][0], b[g][1], b[g][2], b[g][3], uBhi + boff + g * 16 * 80 + ko);
            // Ahi x Bhi
            #pragma unroll
            for (int mi = 0; mi < 2; mi++)
                #pragma unroll
                for (int g = 0; g < 4; g++) {
                    mmabf(acc[mi][2 * g],     ah[mi], b[g][0], b[g][2]);
                    mmabf(acc[mi][2 * g + 1], ah[mi], b[g][1], b[g][3]);
                }
            // Alo x Bhi
            ldsm4(al[0][0], al[0][1], al[0][2], al[0][3], uAlo + aoff + ko);
            ldsm4(al[1][0], al[1][1], al[1][2], al[1][3], uAlo + aoff + 16 * 80 + ko);
            #pragma unroll
            for (int mi = 0; mi < 2; mi++)
                #pragma unroll
                for (int g = 0; g < 4; g++) {
                    mmabf(acc[mi][2 * g],     al[mi], b[g][0], b[g][2]);
                    mmabf(acc[mi][2 * g + 1], al[mi], b[g][1], b[g][3]);
                }
            // Ahi x Blo
            #pragma unroll
            for (int g = 0; g < 4; g++)
                ldsm4(b[g][0], b[g][1], b[g][2], b[g][3], uBlo + boff + g * 16 * 80 + ko);
            #pragma unroll
            for (int mi = 0; mi < 2; mi++)
                #pragma unroll
                for (int g = 0; g < 4; g++) {
                    mmabf(acc[mi][2 * g],     ah[mi], b[g][0], b[g][2]);
                    mmabf(acc[mi][2 * g + 1], ah[mi], b[g][1], b[g][3]);
                }
        }
    }

    // epilogue: bias + relu; write float h and optional bf16 hi/lo split (cols +128)
    #pragma unroll
    for (int mi = 0; mi < 2; mi++) {
        #pragma unroll
        for (int half = 0; half < 2; half++) {
            int node = n0 + mw * 32 + mi * 16 + half * 8 + (lane >> 2);
            if (node < NN) {
                #pragma unroll
                for (int ni = 0; ni < 8; ni++) {
                    int col = nw * 64 + ni * 8 + (lane & 3) * 2;
                    float v0 = fmaxf(acc[mi][ni][half * 2 + 0] + sbias[col], 0.f);
                    float v1 = fmaxf(acc[mi][ni][half * 2 + 1] + sbias[col + 1], 0.f);
                    *(float2*)(outF + (size_t)node * 128 + col) = make_float2(v0, v1);
                    if (outHi) {
                        __nv_bfloat16 h0 = __float2bfloat16(v0), h1 = __float2bfloat16(v1);
                        uint32_t hw = ((uint32_t)__bfloat16_as_ushort(h1) << 16) |
                                      (uint32_t)__bfloat16_as_ushort(h0);
                        uint32_t lw = pack2bf(v0 - __bfloat162float(h0),
                                              v1 - __bfloat162float(h1));
                        *(uint32_t*)(outHi + (size_t)node * 256 + 128 + col) = hw;
                        *(uint32_t*)(outLo + (size_t)node * 256 + 128 + col) = lw;
                    }
                }
            }
        }
    }
}

// ---------------- final 128 -> 2 head ----------------
__global__ void k_head(const float* __restrict__ h, const float* __restrict__ W2,
                       const float* __restrict__ b2, float* __restrict__ out) {
    const int n = blockIdx.x;
    const int t = threadIdx.x;
    float v = h[(size_t)n * DD + t];
    float p0 = v * __ldg(&W2[t]);
    float p1 = v * __ldg(&W2[DD + t]);
    #pragma unroll
    for (int off = 16; off > 0; off >>= 1) {
        p0 += __shfl_down_sync(0xffffffff, p0, off);
        p1 += __shfl_down_sync(0xffffffff, p1, off);
    }
    __shared__ float s0[4], s1[4];
    int w = t >> 5, lane = t & 31;
    if (lane == 0) { s0[w] = p0; s1[w] = p1; }
    __syncthreads();
    if (t == 0) {
        out[n * 2 + 0] = s0[0] + s0[1] + s0[2] + s0[3] + b2[0];
        out[n * 2 + 1] = s1[0] + s1[1] + s1[2] + s1[3] + b2[1];
    }
}

// ---------------- launch ----------------
extern "C" void kernel_launch(void* const* d_in, const int* in_sizes, int n_in,
                              void* d_out, int out_size) {
    const float* x  = (const float*)d_in[0];
    const int*   ei = (const int*)  d_in[1];
    const float* Wl = (const float*)d_in[2];
    const float* bl = (const float*)d_in[3];
    const float* Wr = (const float*)d_in[4];
    const float* W1 = (const float*)d_in[5];
    const float* b1 = (const float*)d_in[6];
    const float* W2 = (const float*)d_in[7];
    const float* b2 = (const float*)d_in[8];
    float* out = (float*)d_out;

    float *h0, *h1;
    __nv_bfloat16 *ahi[2], *alo[2], *bhi, *blo, *w1hi, *w1lo;
    cudaGetSymbolAddress((void**)&h0, g_h0);
    cudaGetSymbolAddress((void**)&h1, g_h1);
    cudaGetSymbolAddress((void**)&ahi[0], g_Ahi0);
    cudaGetSymbolAddress((void**)&alo[0], g_Alo0);
    cudaGetSymbolAddress((void**)&ahi[1], g_Ahi1);
    cudaGetSymbolAddress((void**)&alo[1], g_Alo1);
    cudaGetSymbolAddress((void**)&bhi, g_Bhi);
    cudaGetSymbolAddress((void**)&blo, g_Blo);
    cudaGetSymbolAddress((void**)&w1hi, g_W1hi);
    cudaGetSymbolAddress((void**)&w1lo, g_W1lo);
    float* hb[2] = {h0, h1};

    // CSR build
    k_zero_deg<<<(NN + 255) / 256, 256>>>();
    k_hist<<<(EE + 255) / 256, 256>>>(ei);
    k_blocksum<<<(NN + 255) / 256, 256>>>();
    k_scanpart<<<1, 256>>>();
    k_rowptr<<<(NN + 255) / 256, 256>>>();
    k_fill<<<(EE + 255) / 256, 256>>>(ei);

    // bf16 splits of x and all weights
    k_split_x<<<(NN * DD + 255) / 256, 256>>>(x);
    k_wprep<<<(LL * 128 * 256 + 128 * 128 + 255) / 256, 256>>>(Wl, Wr, W1);

    static const int aggrs[LL] = {0, 1, 2, 0, 1, 2, 0, 1, 2, 0, 2, 1};
    const float* hptr = x;
    int cur = 0;
    for (int i = 0; i < LL; i++) {
        switch (aggrs[i]) {
            case 0: k_agg<0><<<(NN + 7) / 8, 256>>>(hptr, ahi[cur], alo[cur]); break;
            case 1: k_agg<1><<<(NN + 7) / 8, 256>>>(hptr, ahi[cur], alo[cur]); break;
            default: k_agg<2><<<(NN + 7) / 8, 256>>>(hptr, ahi[cur], alo[cur]); break;
        }
        float* hout = hb[i & 1];
        k_tgemm<<<GRID_G, 256>>>(ahi[cur], alo[cur], 256,
                                 bhi + (size_t)i * 128 * 256, blo + (size_t)i * 128 * 256, 256,
                                 bl + (size_t)i * 128, hout, ahi[cur ^ 1], alo[cur ^ 1]);
        hptr = hout;
        cur ^= 1;
    }
    float* mlp = hb[0];
    k_tgemm<<<GRID_G, 256>>>(ahi[cur] + 128, alo[cur] + 128, 256,
                             w1hi, w1lo, 128, b1, mlp, nullptr, nullptr);
    k_head<<<NN, 128>>>(mlp, W2, b2, out);
}

// round 4
// speedup vs baseline: 2.4453x; 1.1060x over previous
#include <cuda_runtime.h>
#include <cuda_bf16.h>
#include <math_constants.h>
#include <cstdint>

#define NN 50000
#define EE 600000
#define DD 128
#define LL 12
#define GRID_G ((NN + 127) / 128)   // 391

#define SROW 40
#define ABYTES (128 * SROW * 2)      // 10240 B per array
#define STAGE_BYTES (4 * ABYTES)     // 40960 B per stage
#define TG_SMEM (2 * STAGE_BYTES + 512)

// ---------------- persistent device scratch ----------------
__device__ float g_h0[NN * DD];
__device__ float g_h1[NN * DD];
__device__ __nv_bfloat16 g_Ahi0[NN * 256];
__device__ __nv_bfloat16 g_Alo0[NN * 256];
__device__ __nv_bfloat16 g_Ahi1[NN * 256];
__device__ __nv_bfloat16 g_Alo1[NN * 256];
__device__ __nv_bfloat16 g_Bhi[LL * 128 * 256];
__device__ __nv_bfloat16 g_Blo[LL * 128 * 256];
__device__ __nv_bfloat16 g_W1hi[128 * 128];
__device__ __nv_bfloat16 g_W1lo[128 * 128];
__device__ int g_rowptr[NN + 1];
__device__ int g_woff[NN];
__device__ int g_csrc[EE];
__device__ int g_deg[NN];
__device__ int g_part[256];
__device__ int g_partscan[256];

// ---------------- helpers ----------------
__device__ __forceinline__ uint32_t s2u(const void* p) {
    uint32_t a;
    asm("{ .reg .u64 t; cvta.to.shared.u64 t, %1; cvt.u32.u64 %0, t; }" : "=r"(a) : "l"(p));
    return a;
}
__device__ __forceinline__ void ldsm4(uint32_t& r0, uint32_t& r1, uint32_t& r2, uint32_t& r3,
                                      uint32_t addr) {
    asm volatile("ldmatrix.sync.aligned.m8n8.x4.shared.b16 {%0,%1,%2,%3}, [%4];"
                 : "=r"(r0), "=r"(r1), "=r"(r2), "=r"(r3) : "r"(addr));
}
__device__ __forceinline__ void mmabf(float* c, const uint32_t* a, uint32_t b0, uint32_t b1) {
    asm volatile(
        "mma.sync.aligned.m16n8k16.row.col.f32.bf16.bf16.f32 "
        "{%0,%1,%2,%3}, {%4,%5,%6,%7}, {%8,%9}, {%0,%1,%2,%3};"
        : "+f"(c[0]), "+f"(c[1]), "+f"(c[2]), "+f"(c[3])
        : "r"(a[0]), "r"(a[1]), "r"(a[2]), "r"(a[3]), "r"(b0), "r"(b1));
}
__device__ __forceinline__ uint32_t pack2bf(float a, float b) {
    __nv_bfloat16 ha = __float2bfloat16(a), hb = __float2bfloat16(b);
    return ((uint32_t)__bfloat16_as_ushort(hb) << 16) | (uint32_t)__bfloat16_as_ushort(ha);
}
__device__ __forceinline__ void cpasync16(uint32_t dst, const void* src) {
    asm volatile("cp.async.cg.shared.global [%0], [%1], 16;" :: "r"(dst), "l"(src));
}

// ---------------- CSR build ----------------
__global__ void k_zero_deg() {
    int i = blockIdx.x * blockDim.x + threadIdx.x;
    if (i < NN) g_deg[i] = 0;
}
__global__ void k_hist(const int* __restrict__ ei) {
    int e = blockIdx.x * blockDim.x + threadIdx.x;
    if (e < EE) atomicAdd(&g_deg[ei[EE + e]], 1);
}
__global__ void k_blocksum() {
    __shared__ int sm[256];
    int t = threadIdx.x;
    int i = blockIdx.x * 256 + t;
    sm[t] = (i < NN) ? g_deg[i] : 0;
    __syncthreads();
    for (int o = 128; o > 0; o >>= 1) {
        if (t < o) sm[t] += sm[t + o];
        __syncthreads();
    }
    if (t == 0) g_part[blockIdx.x] = sm[0];
}
__global__ void k_scanpart() {
    __shared__ int sm[256];
    int t = threadIdx.x;
    int v = (t < 196) ? g_part[t] : 0;
    sm[t] = v;
    __syncthreads();
    for (int o = 1; o < 256; o <<= 1) {
        int u = (t >= o) ? sm[t - o] : 0;
        __syncthreads();
        sm[t] += u;
        __syncthreads();
    }
    g_partscan[t] = sm[t] - v;
    if (t == 0) g_rowptr[NN] = EE;
}
__global__ void k_rowptr() {
    __shared__ int sm[256];
    int t = threadIdx.x;
    int i = blockIdx.x * 256 + t;
    int v = (i < NN) ? g_deg[i] : 0;
    sm[t] = v;
    __syncthreads();
    for (int o = 1; o < 256; o <<= 1) {
        int u = (t >= o) ? sm[t - o] : 0;
        __syncthreads();
        sm[t] += u;
        __syncthreads();
    }
    if (i < NN) {
        int ex = g_partscan[blockIdx.x] + sm[t] - v;
        g_rowptr[i] = ex;
        g_woff[i] = ex;
    }
}
__global__ void k_fill(const int* __restrict__ ei) {
    int e = blockIdx.x * blockDim.x + threadIdx.x;
    if (e < EE) {
        int d = ei[EE + e];
        int p = atomicAdd(&g_woff[d], 1);
        g_csrc[p] = ei[e];
    }
}

// ---------------- bf16 split preprocessing ----------------
__global__ void k_split_x(const float* __restrict__ x) {
    int i = blockIdx.x * 256 + threadIdx.x;
    if (i < NN * DD) {
        int n = i >> 7, k = i & 127;
        float v = x[i];
        __nv_bfloat16 h = __float2bfloat16(v);
        g_Ahi0[n * 256 + 128 + k] = h;
        g_Alo0[n * 256 + 128 + k] = __float2bfloat16(v - __bfloat162float(h));
    }
}
__global__ void k_wprep(const float* __restrict__ Wl, const float* __restrict__ Wr,
                        const float* __restrict__ W1) {
    int i = blockIdx.x * 256 + threadIdx.x;
    const int tot = LL * 128 * 256;
    if (i < tot) {
        int l = i / 32768;
        int r = (i >> 8) & 127;
        int c = i & 255;
        float v = (c < 128) ? Wl[l * 16384 + r * 128 + c] : Wr[l * 16384 + r * 128 + (c - 128)];
        __nv_bfloat16 h = __float2bfloat16(v);
        g_Bhi[i] = h;
        g_Blo[i] = __float2bfloat16(v - __bfloat162float(h));
    } else {
        int j = i - tot;
        if (j < 16384) {
            float v = W1[j];
            __nv_bfloat16 h = __float2bfloat16(v);
            g_W1hi[j] = h;
            g_W1lo[j] = __float2bfloat16(v - __bfloat162float(h));
        }
    }
}

// ---------------- aggregation: warp per node, 4-edge unroll ----------------
template <int AGGR>
__global__ void k_agg(const float* __restrict__ h,
                      __nv_bfloat16* __restrict__ Ahi, __nv_bfloat16* __restrict__ Alo) {
    int wid = threadIdx.x >> 5, lane = threadIdx.x & 31;
    int v = blockIdx.x * 8 + wid;
    if (v >= NN) return;
    int beg = g_rowptr[v], end = g_rowptr[v + 1];
    float a0, a1, a2, a3;
    if (AGGR == 2) { a0 = a1 = a2 = a3 = -CUDART_INF_F; }
    else           { a0 = a1 = a2 = a3 = 0.f; }
    const int fo = lane * 4;
    int j = beg;
    for (; j + 3 < end; j += 4) {
        int s0 = __ldg(&g_csrc[j]);
        int s1 = __ldg(&g_csrc[j + 1]);
        int s2 = __ldg(&g_csrc[j + 2]);
        int s3 = __ldg(&g_csrc[j + 3]);
        float4 x0 = *(const float4*)(h + (size_t)s0 * DD + fo);
        float4 x1 = *(const float4*)(h + (size_t)s1 * DD + fo);
        float4 x2 = *(const float4*)(h + (size_t)s2 * DD + fo);
        float4 x3 = *(const float4*)(h + (size_t)s3 * DD + fo);
        if (AGGR == 2) {
            a0 = fmaxf(a0, fmaxf(fmaxf(x0.x, x1.x), fmaxf(x2.x, x3.x)));
            a1 = fmaxf(a1, fmaxf(fmaxf(x0.y, x1.y), fmaxf(x2.y, x3.y)));
            a2 = fmaxf(a2, fmaxf(fmaxf(x0.z, x1.z), fmaxf(x2.z, x3.z)));
            a3 = fmaxf(a3, fmaxf(fmaxf(x0.w, x1.w), fmaxf(x2.w, x3.w)));
        } else {
            a0 += (x0.x + x1.x) + (x2.x + x3.x);
            a1 += (x0.y + x1.y) + (x2.y + x3.y);
            a2 += (x0.z + x1.z) + (x2.z + x3.z);
            a3 += (x0.w + x1.w) + (x2.w + x3.w);
        }
    }
    for (; j < end; j++) {
        int s0 = __ldg(&g_csrc[j]);
        float4 x0 = *(const float4*)(h + (size_t)s0 * DD + fo);
        if (AGGR == 2) {
            a0 = fmaxf(a0, x0.x); a1 = fmaxf(a1, x0.y);
            a2 = fmaxf(a2, x0.z); a3 = fmaxf(a3, x0.w);
        } else {
            a0 += x0.x; a1 += x0.y; a2 += x0.z; a3 += x0.w;
        }
    }
    if (AGGR == 1) {
        int deg = end - beg;
        float inv = (deg > 0) ? (1.0f / (float)deg) : 0.f;
        a0 *= inv; a1 *= inv; a2 *= inv; a3 *= inv;
    }
    if (AGGR == 2) {
        if (isinf(a0) && a0 < 0.f) a0 = 0.f;
        if (isinf(a1) && a1 < 0.f) a1 = 0.f;
        if (isinf(a2) && a2 < 0.f) a2 = 0.f;
        if (isinf(a3) && a3 < 0.f) a3 = 0.f;
    }
    __nv_bfloat16 h0 = __float2bfloat16(a0), h1 = __float2bfloat16(a1);
    __nv_bfloat16 h2 = __float2bfloat16(a2), h3 = __float2bfloat16(a3);
    uint32_t hi01 = ((uint32_t)__bfloat16_as_ushort(h1) << 16) | __bfloat16_as_ushort(h0);
    uint32_t hi23 = ((uint32_t)__bfloat16_as_ushort(h3) << 16) | __bfloat16_as_ushort(h2);
    uint32_t lo01 = pack2bf(a0 - __bfloat162float(h0), a1 - __bfloat162float(h1));
    uint32_t lo23 = pack2bf(a2 - __bfloat162float(h2), a3 - __bfloat162float(h3));
    *(uint2*)(Ahi + (size_t)v * 256 + fo) = make_uint2(hi01, hi23);
    *(uint2*)(Alo + (size_t)v * 256 + fo) = make_uint2(lo01, lo23);
}

// ---------------- HMMA bf16x3 GEMM, cp.async double-buffered ----------------
__device__ __forceinline__ void stage_chunk(
    uint32_t sbase, const __nv_bfloat16* __restrict__ Ahi,
    const __nv_bfloat16* __restrict__ Alo, int astride,
    const __nv_bfloat16* __restrict__ Bhi, const __nv_bfloat16* __restrict__ Blo,
    int Kd, int n0, int kk, int t) {
    #pragma unroll
    for (int i = 0; i < 8; i++) {
        int idx = i * 256 + t;
        int arr = idx >> 9;
        int row = (idx >> 2) & 127;
        int q = idx & 3;
        const __nv_bfloat16* g;
        if (arr < 2) {
            int gr = n0 + row; if (gr >= NN) gr = NN - 1;
            g = ((arr == 0) ? Ahi : Alo) + (size_t)gr * astride + kk + q * 8;
        } else {
            g = ((arr == 2) ? Bhi : Blo) + (size_t)row * Kd + kk + q * 8;
        }
        cpasync16(sbase + arr * ABYTES + row * 80 + q * 16, g);
    }
    asm volatile("cp.async.commit_group;" ::: "memory");
}

__global__ __launch_bounds__(256, 2)
void k_tgemm(const __nv_bfloat16* __restrict__ Ahi, const __nv_bfloat16* __restrict__ Alo,
             int astride,
             const __nv_bfloat16* __restrict__ Bhi, const __nv_bfloat16* __restrict__ Blo,
             int Kd, const float* __restrict__ bias, float* __restrict__ outF,
             __nv_bfloat16* outHi, __nv_bfloat16* outLo) {
    extern __shared__ char smem[];
    float* sbias = (float*)(smem + 2 * STAGE_BYTES);

    const int t = threadIdx.x;
    const int lane = t & 31;
    const int wid = t >> 5;
    const int mw = wid & 3;
    const int nw = wid >> 2;
    const int n0 = blockIdx.x * 128;

    if (t < 128) sbias[t] = bias[t];

    const uint32_t sb0 = s2u(smem);
    const uint32_t sb1 = sb0 + STAGE_BYTES;
    const uint32_t aoff = (uint32_t)((mw * 32 + (lane & 15)) * 80 + (lane >> 4) * 16);
    const uint32_t boff = (uint32_t)((nw * 64 + ((lane >> 3) & 1) * 8 + (lane & 7)) * 80 +
                                     (lane >> 4) * 16);

    float acc[2][8][4];
    #pragma unroll
    for (int mi = 0; mi < 2; mi++)
        #pragma unroll
        for (int ni = 0; ni < 8; ni++)
            #pragma unroll
            for (int q = 0; q < 4; q++) acc[mi][ni][q] = 0.f;

    const int nch = Kd >> 5;
    stage_chunk(sb0, Ahi, Alo, astride, Bhi, Blo, Kd, n0, 0, t);

    for (int c = 0; c < nch; c++) {
        const uint32_t cur = (c & 1) ? sb1 : sb0;
        if (c + 1 < nch) {
            stage_chunk((c & 1) ? sb0 : sb1, Ahi, Alo, astride, Bhi, Blo, Kd,
                        n0, (c + 1) << 5, t);
            asm volatile("cp.async.wait_group 1;" ::: "memory");
        } else {
            asm volatile("cp.async.wait_group 0;" ::: "memory");
        }
        __syncthreads();

        const uint32_t uAhi = cur, uAlo = cur + ABYTES;
        const uint32_t uBhi = cur + 2 * ABYTES, uBlo = cur + 3 * ABYTES;
        #pragma unroll
        for (int ks = 0; ks < 2; ks++) {
            const uint32_t ko = ks * 32;
            uint32_t ah[2][4], al[2][4], b[4][4];
            ldsm4(ah[0][0], ah[0][1], ah[0][2], ah[0][3], uAhi + aoff + ko);
            ldsm4(ah[1][0], ah[1][1], ah[1][2], ah[1][3], uAhi + aoff + 16 * 80 + ko);
            #pragma unroll
            for (int g = 0; g < 4; g++)
                ldsm4(b[g][0], b[g][1], b[g][2], b[g][3], uBhi + boff + g * 16 * 80 + ko);
            #pragma unroll
            for (int mi = 0; mi < 2; mi++)
                #pragma unroll
                for (int g = 0; g < 4; g++) {
                    mmabf(acc[mi][2 * g],     ah[mi], b[g][0], b[g][2]);
                    mmabf(acc[mi][2 * g + 1], ah[mi], b[g][1], b[g][3]);
                }
            ldsm4(al[0][0], al[0][1], al[0][2], al[0][3], uAlo + aoff + ko);
            ldsm4(al[1][0], al[1][1], al[1][2], al[1][3], uAlo + aoff + 16 * 80 + ko);
            #pragma unroll
            for (int mi = 0; mi < 2; mi++)
                #pragma unroll
                for (int g = 0; g < 4; g++) {
                    mmabf(acc[mi][2 * g],     al[mi], b[g][0], b[g][2]);
                    mmabf(acc[mi][2 * g + 1], al[mi], b[g][1], b[g][3]);
                }
            #pragma unroll
            for (int g = 0; g < 4; g++)
                ldsm4(b[g][0], b[g][1], b[g][2], b[g][3], uBlo + boff + g * 16 * 80 + ko);
            #pragma unroll
            for (int mi = 0; mi < 2; mi++)
                #pragma unroll
                for (int g = 0; g < 4; g++) {
                    mmabf(acc[mi][2 * g],     ah[mi], b[g][0], b[g][2]);
                    mmabf(acc[mi][2 * g + 1], ah[mi], b[g][1], b[g][3]);
                }
        }
        __syncthreads();
    }

    #pragma unroll
    for (int mi = 0; mi < 2; mi++) {
        #pragma unroll
        for (int half = 0; half < 2; half++) {
            int node = n0 + mw * 32 + mi * 16 + half * 8 + (lane >> 2);
            if (node < NN) {
                #pragma unroll
                for (int ni = 0; ni < 8; ni++) {
                    int col = nw * 64 + ni * 8 + (lane & 3) * 2;
                    float v0 = fmaxf(acc[mi][ni][half * 2 + 0] + sbias[col], 0.f);
                    float v1 = fmaxf(acc[mi][ni][half * 2 + 1] + sbias[col + 1], 0.f);
                    *(float2*)(outF + (size_t)node * 128 + col) = make_float2(v0, v1);
                    if (outHi) {
                        __nv_bfloat16 h0 = __float2bfloat16(v0), h1 = __float2bfloat16(v1);
                        uint32_t hw = ((uint32_t)__bfloat16_as_ushort(h1) << 16) |
                                      (uint32_t)__bfloat16_as_ushort(h0);
                        uint32_t lw = pack2bf(v0 - __bfloat162float(h0),
                                              v1 - __bfloat162float(h1));
                        *(uint32_t*)(outHi + (size_t)node * 256 + 128 + col) = hw;
                        *(uint32_t*)(outLo + (size_t)node * 256 + 128 + col) = lw;
                    }
                }
            }
        }
    }
}

// ---------------- final 128 -> 2 head ----------------
__global__ void k_head(const float* __restrict__ h, const float* __restrict__ W2,
                       const float* __restrict__ b2, float* __restrict__ out) {
    const int n = blockIdx.x;
    const int t = threadIdx.x;
    float v = h[(size_t)n * DD + t];
    float p0 = v * __ldg(&W2[t]);
    float p1 = v * __ldg(&W2[DD + t]);
    #pragma unroll
    for (int off = 16; off > 0; off >>= 1) {
        p0 += __shfl_down_sync(0xffffffff, p0, off);
        p1 += __shfl_down_sync(0xffffffff, p1, off);
    }
    __shared__ float s0[4], s1[4];
    int w = t >> 5, lane = t & 31;
    if (lane == 0) { s0[w] = p0; s1[w] = p1; }
    __syncthreads();
    if (t == 0) {
        out[n * 2 + 0] = s0[0] + s0[1] + s0[2] + s0[3] + b2[0];
        out[n * 2 + 1] = s1[0] + s1[1] + s1[2] + s1[3] + b2[1];
    }
}

// ---------------- launch ----------------
extern "C" void kernel_launch(void* const* d_in, const int* in_sizes, int n_in,
                              void* d_out, int out_size) {
    const float* x  = (const float*)d_in[0];
    const int*   ei = (const int*)  d_in[1];
    const float* Wl = (const float*)d_in[2];
    const float* bl = (const float*)d_in[3];
    const float* Wr = (const float*)d_in[4];
    const float* W1 = (const float*)d_in[5];
    const float* b1 = (const float*)d_in[6];
    const float* W2 = (const float*)d_in[7];
    const float* b2 = (const float*)d_in[8];
    float* out = (float*)d_out;

    float *h0, *h1;
    __nv_bfloat16 *ahi[2], *alo[2], *bhi, *blo, *w1hi, *w1lo;
    cudaGetSymbolAddress((void**)&h0, g_h0);
    cudaGetSymbolAddress((void**)&h1, g_h1);
    cudaGetSymbolAddress((void**)&ahi[0], g_Ahi0);
    cudaGetSymbolAddress((void**)&alo[0], g_Alo0);
    cudaGetSymbolAddress((void**)&ahi[1], g_Ahi1);
    cudaGetSymbolAddress((void**)&alo[1], g_Alo1);
    cudaGetSymbolAddress((void**)&bhi, g_Bhi);
    cudaGetSymbolAddress((void**)&blo, g_Blo);
    cudaGetSymbolAddress((void**)&w1hi, g_W1hi);
    cudaGetSymbolAddress((void**)&w1lo, g_W1lo);
    float* hb[2] = {h0, h1};

    cudaFuncSetAttribute(k_tgemm, cudaFuncAttributeMaxDynamicSharedMemorySize, TG_SMEM);

    // CSR build
    k_zero_deg<<<(NN + 255) / 256, 256>>>();
    k_hist<<<(EE + 255) / 256, 256>>>(ei);
    k_blocksum<<<(NN + 255) / 256, 256>>>();
    k_scanpart<<<1, 256>>>();
    k_rowptr<<<(NN + 255) / 256, 256>>>();
    k_fill<<<(EE + 255) / 256, 256>>>(ei);

    // bf16 splits of x and all weights
    k_split_x<<<(NN * DD + 255) / 256, 256>>>(x);
    k_wprep<<<(LL * 128 * 256 + 128 * 128 + 255) / 256, 256>>>(Wl, Wr, W1);

    static const int aggrs[LL] = {0, 1, 2, 0, 1, 2, 0, 1, 2, 0, 2, 1};
    const float* hptr = x;
    int cur = 0;
    for (int i = 0; i < LL; i++) {
        switch (aggrs[i]) {
            case 0: k_agg<0><<<(NN + 7) / 8, 256>>>(hptr, ahi[cur], alo[cur]); break;
            case 1: k_agg<1><<<(NN + 7) / 8, 256>>>(hptr, ahi[cur], alo[cur]); break;
            default: k_agg<2><<<(NN + 7) / 8, 256>>>(hptr, ahi[cur], alo[cur]); break;
        }
        float* hout = hb[i & 1];
        k_tgemm<<<GRID_G, 256, TG_SMEM>>>(ahi[cur], alo[cur], 256,
                                          bhi + (size_t)i * 128 * 256,
                                          blo + (size_t)i * 128 * 256, 256,
                                          bl + (size_t)i * 128, hout,
                                          ahi[cur ^ 1], alo[cur ^ 1]);
        hptr = hout;
        cur ^= 1;
    }
    float* mlp = hb[0];
    k_tgemm<<<GRID_G, 256, TG_SMEM>>>(ahi[cur] + 128, alo[cur] + 128, 256,
                                      w1hi, w1lo, 128, b1, mlp, nullptr, nullptr);
    k_head<<<NN, 128>>>(mlp, W2, b2, out);
}